// round 11
// baseline (speedup 1.0000x reference)
#include <cuda_runtime.h>
#include <cuda_bf16.h>
#include <math.h>
#include <stdint.h>

#define BATCH   2048
#define NGENES  4096
#define MAXCH   5120
#define OUTCOLS 341

// ---------------------------------------------------------------------------
// Static device buffers
// ---------------------------------------------------------------------------
__device__ float g_bufA[BATCH * MAXCH];
__device__ float g_bufB[BATCH * MAXCH];
__device__ float g_mu[MAXCH];
__device__ float g_rstd[MAXCH];
__device__ float g_psum[32 * MAXCH];
__device__ float g_psqr[32 * MAXCH];
__device__ float g_part[4 * BATCH * 1232];        // K-split partials (40 MB)
__device__ __nv_bfloat16 g_Ahi[25165824];         // max B*T*Ipad (s3: 2048*64*192)
__device__ __nv_bfloat16 g_Alo[25165824];
__device__ __nv_bfloat16 g_Whi[6607104];
__device__ __nv_bfloat16 g_Wlo[6607104];

__device__ __forceinline__ float* bufptr(int sel) { return sel == 0 ? g_bufA : g_bufB; }

__device__ __forceinline__ uint32_t smem_u32(const void* p) {
    uint32_t a;
    asm("{ .reg .u64 t; cvta.to.shared.u64 t, %1; cvt.u32.u64 %0, t; }" : "=r"(a) : "l"(p));
    return a;
}
__device__ __forceinline__ float tanh_fast(float x) {
    float y;
    asm("tanh.approx.f32 %0, %1;" : "=f"(y) : "f"(x));
    return y;
}
__device__ __forceinline__ uint16_t bf16bits(float v) {
    __nv_bfloat16 h = __float2bfloat16(v);
    return *reinterpret_cast<uint16_t*>(&h);
}
__device__ __forceinline__ float bf16val(uint16_t u) {
    __nv_bfloat16 h = *reinterpret_cast<__nv_bfloat16*>(&u);
    return __bfloat162float(h);
}

#define CP_ASYNC16(dst, src, sz) \
    asm volatile("cp.async.cg.shared.global [%0], [%1], 16, %2;" \
                 :: "r"(dst), "l"(src), "r"(sz))
#define CP_COMMIT()  asm volatile("cp.async.commit_group;" ::: "memory")
#define CP_WAIT(N)   asm volatile("cp.async.wait_group %0;" :: "n"(N) : "memory")

__device__ __forceinline__ void ldsm4(uint32_t& r0, uint32_t& r1, uint32_t& r2,
                                      uint32_t& r3, uint32_t addr) {
    asm volatile("ldmatrix.sync.aligned.m8n8.x4.shared.b16 {%0,%1,%2,%3}, [%4];"
                 : "=r"(r0), "=r"(r1), "=r"(r2), "=r"(r3) : "r"(addr));
}
__device__ __forceinline__ void mma16816(float* d, uint32_t a0, uint32_t a1,
                                         uint32_t a2, uint32_t a3,
                                         uint32_t b0, uint32_t b1) {
    asm volatile("mma.sync.aligned.m16n8k16.row.col.f32.bf16.bf16.f32 "
                 "{%0,%1,%2,%3}, {%4,%5,%6,%7}, {%8,%9}, {%0,%1,%2,%3};"
                 : "+f"(d[0]), "+f"(d[1]), "+f"(d[2]), "+f"(d[3])
                 : "r"(a0), "r"(a1), "r"(a2), "r"(a3), "r"(b0), "r"(b1));
}

// ---------------------------------------------------------------------------
// Tiny-strata GEMM (s4 only: I=16, O=20) + fused partial batch stats.
// 256 threads, 512 batch rows/block (2 rows/thread), grid (4, T).
// ---------------------------------------------------------------------------
__global__ void __launch_bounds__(256) tiny_kernel(
    int aSel, int chPrev, const float* __restrict__ x,
    const float* __restrict__ W, const float* __restrict__ bias, int hSel,
    int I, int Gs, int split, int CH)
{
    __shared__ float sW[144 * 20];
    __shared__ float sb2[20];
    __shared__ float sS[8 * 20], sQ[8 * 20];
    const float* act = (aSel >= 0) ? bufptr(aSel) : nullptr;
    float* h = bufptr(hSel);
    int t = blockIdx.y;
    int wid = threadIdx.x >> 5, lane = threadIdx.x & 31;
    const float* Wt = W + (size_t)t * I * 20;
    for (int i = threadIdx.x; i < I * 20; i += 256) sW[i] = Wt[i];
    if (threadIdx.x < 20) sb2[threadIdx.x] = bias[t * 20 + threadIdx.x];
    __syncthreads();

    int b0 = blockIdx.x * 512 + threadIdx.x;
    int b1 = b0 + 256;
    float a0c[20], a1c[20];
#pragma unroll
    for (int o = 0; o < 20; o++) { a0c[o] = sb2[o]; a1c[o] = sb2[o]; }

    const float* w = sW;
    if (split > 0) {
        const float* p0 = act + (size_t)b0 * chPrev + (size_t)t * split;
        const float* p1 = act + (size_t)b1 * chPrev + (size_t)t * split;
        for (int k4 = 0; k4 < split; k4 += 4) {
            float4 v0 = *reinterpret_cast<const float4*>(p0 + k4);
            float4 v1 = *reinterpret_cast<const float4*>(p1 + k4);
            const float a0v[4] = {v0.x, v0.y, v0.z, v0.w};
            const float a1v[4] = {v1.x, v1.y, v1.z, v1.w};
#pragma unroll
            for (int kk = 0; kk < 4; kk++) {
#pragma unroll
                for (int o = 0; o < 20; o++) {
                    float ww = w[o];
                    a0c[o] = fmaf(a0v[kk], ww, a0c[o]);
                    a1c[o] = fmaf(a1v[kk], ww, a1c[o]);
                }
                w += 20;
            }
        }
    }
    {
        const float* q0 = x + (size_t)b0 * NGENES + (size_t)t * Gs;
        const float* q1 = x + (size_t)b1 * NGENES + (size_t)t * Gs;
        int I2 = I - split;
        for (int k4 = 0; k4 < I2; k4 += 4) {
            float4 v0 = *reinterpret_cast<const float4*>(q0 + k4);
            float4 v1 = *reinterpret_cast<const float4*>(q1 + k4);
            const float a0v[4] = {v0.x, v0.y, v0.z, v0.w};
            const float a1v[4] = {v1.x, v1.y, v1.z, v1.w};
#pragma unroll
            for (int kk = 0; kk < 4; kk++) {
#pragma unroll
                for (int o = 0; o < 20; o++) {
                    float ww = w[o];
                    a0c[o] = fmaf(a0v[kk], ww, a0c[o]);
                    a1c[o] = fmaf(a1v[kk], ww, a1c[o]);
                }
                w += 20;
            }
        }
    }
    float* h0 = h + (size_t)b0 * CH + t * 20;
    float* h1 = h + (size_t)b1 * CH + t * 20;
#pragma unroll
    for (int o = 0; o < 20; o++) { h0[o] = a0c[o]; h1[o] = a1c[o]; }

#pragma unroll
    for (int o = 0; o < 20; o++) {
        float s = a0c[o] + a1c[o];
        float q = a0c[o] * a0c[o] + a1c[o] * a1c[o];
#pragma unroll
        for (int off = 16; off; off >>= 1) {
            s += __shfl_xor_sync(0xffffffffu, s, off);
            q += __shfl_xor_sync(0xffffffffu, q, off);
        }
        if (lane == 0) { sS[wid * 20 + o] = s; sQ[wid * 20 + o] = q; }
    }
    __syncthreads();
    if (threadIdx.x < 20) {
        float S = 0.f, Q = 0.f;
#pragma unroll
        for (int ww = 0; ww < 8; ww++) { S += sS[ww * 20 + threadIdx.x]; Q += sQ[ww * 20 + threadIdx.x]; }
        g_psum[blockIdx.x * MAXCH + t * 20 + threadIdx.x] = S;
        g_psqr[blockIdx.x * MAXCH + t * 20 + threadIdx.x] = Q;
    }
}

// ---------------------------------------------------------------------------
// prepA (x4 vectorized): gather + zero-pad + bf16 hi/lo split.
// ---------------------------------------------------------------------------
__global__ void __launch_bounds__(256) prepA_kernel(
    int aSel, int chPrev, const float* __restrict__ x,
    int T, int I, int Ipad, int Gs, int split)
{
    int idx4 = blockIdx.x * 256 + threadIdx.x;
    int TIp4 = T * (Ipad >> 2);
    int b = idx4 / TIp4;
    int rem = idx4 - b * TIp4;
    int t = rem / (Ipad >> 2);
    int i = (rem - t * (Ipad >> 2)) << 2;
    const float* act = (aSel >= 0) ? bufptr(aSel) : nullptr;
    float4 v = make_float4(0.f, 0.f, 0.f, 0.f);
    if (i < split)
        v = *reinterpret_cast<const float4*>(act + (size_t)b * chPrev + t * split + i);
    else if (i < I)
        v = *reinterpret_cast<const float4*>(x + (size_t)b * NGENES + t * Gs + (i - split));
    uint16_t h0 = bf16bits(v.x), h1 = bf16bits(v.y), h2 = bf16bits(v.z), h3 = bf16bits(v.w);
    uint16_t l0 = bf16bits(v.x - bf16val(h0)), l1 = bf16bits(v.y - bf16val(h1));
    uint16_t l2 = bf16bits(v.z - bf16val(h2)), l3 = bf16bits(v.w - bf16val(h3));
    uint2 ph = make_uint2((uint32_t)h0 | ((uint32_t)h1 << 16), (uint32_t)h2 | ((uint32_t)h3 << 16));
    uint2 pl = make_uint2((uint32_t)l0 | ((uint32_t)l1 << 16), (uint32_t)l2 | ((uint32_t)l3 << 16));
    reinterpret_cast<uint2*>(g_Ahi)[idx4] = ph;
    reinterpret_cast<uint2*>(g_Alo)[idx4] = pl;
}

// ---------------------------------------------------------------------------
// prepW: transpose W[t][i][o] -> Wt[t][o][i], pad i to Ipad, bf16 hi/lo.
// ---------------------------------------------------------------------------
__global__ void __launch_bounds__(256) prepW_kernel(
    const float* __restrict__ W, int I, int Ipad, int O)
{
    __shared__ float tile[32][33];
    int t = blockIdx.z;
    int i0 = blockIdx.x * 32, o0 = blockIdx.y * 32;
    int tx = threadIdx.x, ty = threadIdx.y;   // 32 x 8
    const float* Wt = W + (size_t)t * I * O;
#pragma unroll
    for (int j = 0; j < 4; j++) {
        int i = i0 + ty + j * 8, o = o0 + tx;
        tile[ty + j * 8][tx] = (i < I && o < O) ? Wt[(size_t)i * O + o] : 0.f;
    }
    __syncthreads();
#pragma unroll
    for (int j = 0; j < 4; j++) {
        int o = o0 + ty + j * 8, i = i0 + tx;
        if (o < O) {
            float v = tile[tx][ty + j * 8];
            __nv_bfloat16 hi = __float2bfloat16(v);
            size_t oi = ((size_t)t * O + o) * Ipad + i;
            g_Whi[oi] = hi;
            g_Wlo[oi] = __float2bfloat16(v - __bfloat162float(hi));
        }
    }
}

// ---------------------------------------------------------------------------
// HMMA GEMM, optionally K-split. CTA 128x128, 8 warps, K-chunk 32, 3-stage.
// blockIdx.z = t * kSplit + splitIdx.
// ---------------------------------------------------------------------------
#define ROWB     80
#define REG_SZ   10240
#define BUF_SZ   (4 * REG_SZ)
#define SM_GEMM  (3 * BUF_SZ)

__global__ void __launch_bounds__(256, 1) mma_gemm_kernel(
    const float* __restrict__ bias, int hSel, int T, int Ipad, int O, int CH,
    int kSplit)
{
    extern __shared__ char smem[];
    uint32_t sb = smem_u32(smem);
    float* h = bufptr(hSel);
    int tid = threadIdx.x, wid = tid >> 5, lane = tid & 31;
    int t  = blockIdx.z / kSplit;
    int sp = blockIdx.z - t * kSplit;
    int b0 = blockIdx.y * 128, n0 = blockIdx.x * 128;
    int m0w = (wid >> 2) * 64;
    int n0w = (wid & 3) * 32;
    int nCtot = Ipad >> 5;
    int nC = nCtot / kSplit;
    int cBase = sp * nC;
    int Arow = T * Ipad;

    float acc[4][4][4];
#pragma unroll
    for (int a = 0; a < 4; a++)
#pragma unroll
        for (int b = 0; b < 4; b++)
#pragma unroll
            for (int c = 0; c < 4; c++) acc[a][b][c] = 0.f;

    int r0 = (tid + 0) >> 2,   c0 = (tid + 0) & 3;
    int r1 = (tid + 256) >> 2, c1 = (tid + 256) & 3;
    int bn0ok = (n0 + r0 < O) ? 16 : 0;
    int bn1ok = (n0 + r1 < O) ? 16 : 0;
    size_t aOff0 = (size_t)(b0 + r0) * Arow + (size_t)t * Ipad + c0 * 8;
    size_t aOff1 = (size_t)(b0 + r1) * Arow + (size_t)t * Ipad + c1 * 8;
    size_t bOff0 = ((size_t)t * O + min(n0 + r0, O - 1)) * Ipad + c0 * 8;
    size_t bOff1 = ((size_t)t * O + min(n0 + r1, O - 1)) * Ipad + c1 * 8;
    uint32_t d0 = r0 * ROWB + c0 * 16;
    uint32_t d1 = r1 * ROWB + c1 * 16;

#define LOAD_CHUNK(lIdx) do {                                                  \
        uint32_t base = sb + ((lIdx) % 3) * BUF_SZ;                            \
        int k0 = (cBase + (lIdx)) << 5;                                        \
        CP_ASYNC16(base + d0,              g_Ahi + aOff0 + k0, 16);            \
        CP_ASYNC16(base + d1,              g_Ahi + aOff1 + k0, 16);            \
        CP_ASYNC16(base + REG_SZ + d0,     g_Alo + aOff0 + k0, 16);            \
        CP_ASYNC16(base + REG_SZ + d1,     g_Alo + aOff1 + k0, 16);            \
        CP_ASYNC16(base + 2 * REG_SZ + d0, g_Whi + bOff0 + k0, bn0ok);         \
        CP_ASYNC16(base + 2 * REG_SZ + d1, g_Whi + bOff1 + k0, bn1ok);         \
        CP_ASYNC16(base + 3 * REG_SZ + d0, g_Wlo + bOff0 + k0, bn0ok);         \
        CP_ASYNC16(base + 3 * REG_SZ + d1, g_Wlo + bOff1 + k0, bn1ok);         \
        CP_COMMIT();                                                           \
    } while (0)

    uint32_t aRowSel = (lane & 15);
    uint32_t aKHalf  = (lane >> 4) * 16;
    uint32_t bRowSel = (lane & 7) + ((lane >> 4) << 3);
    uint32_t bKHalf  = ((lane >> 3) & 1) * 16;

    LOAD_CHUNK(0);
    LOAD_CHUNK(1);

    for (int l = 0; l < nC; l++) {
        if (l + 2 < nC) LOAD_CHUNK(l + 2);
        else            CP_COMMIT();
        CP_WAIT(2);
        __syncthreads();

        uint32_t base = sb + (l % 3) * BUF_SZ;
        uint32_t aHi = base;
        uint32_t aLo = base + REG_SZ;
        uint32_t bHi = base + 2 * REG_SZ;
        uint32_t bLo = base + 3 * REG_SZ;

#pragma unroll
        for (int ks = 0; ks < 2; ks++) {
            uint32_t kOffA = ks * 32 + aKHalf;
            uint32_t kOffB = ks * 32 + bKHalf;
            uint32_t ah[4][4], al[4][4], bh[4][2], bl[4][2];
#pragma unroll
            for (int mt = 0; mt < 4; mt++) {
                uint32_t ra = (m0w + mt * 16 + aRowSel) * ROWB + kOffA;
                ldsm4(ah[mt][0], ah[mt][1], ah[mt][2], ah[mt][3], aHi + ra);
                ldsm4(al[mt][0], al[mt][1], al[mt][2], al[mt][3], aLo + ra);
            }
#pragma unroll
            for (int np = 0; np < 2; np++) {
                uint32_t rb = (n0w + np * 16 + bRowSel) * ROWB + kOffB;
                uint32_t q0, q1, q2, q3;
                ldsm4(q0, q1, q2, q3, bHi + rb);
                bh[np * 2][0] = q0; bh[np * 2][1] = q1;
                bh[np * 2 + 1][0] = q2; bh[np * 2 + 1][1] = q3;
                ldsm4(q0, q1, q2, q3, bLo + rb);
                bl[np * 2][0] = q0; bl[np * 2][1] = q1;
                bl[np * 2 + 1][0] = q2; bl[np * 2 + 1][1] = q3;
            }
#pragma unroll
            for (int mt = 0; mt < 4; mt++)
#pragma unroll
                for (int nt = 0; nt < 4; nt++) {
                    mma16816(acc[mt][nt], ah[mt][0], ah[mt][1], ah[mt][2], ah[mt][3],
                             bh[nt][0], bh[nt][1]);
                    mma16816(acc[mt][nt], ah[mt][0], ah[mt][1], ah[mt][2], ah[mt][3],
                             bl[nt][0], bl[nt][1]);
                    mma16816(acc[mt][nt], al[mt][0], al[mt][1], al[mt][2], al[mt][3],
                             bh[nt][0], bh[nt][1]);
                }
        }
        __syncthreads();
    }
    CP_WAIT(0);
    __syncthreads();

    if (kSplit > 1) {
        float* pb = g_part + (size_t)sp * BATCH * CH;
#pragma unroll
        for (int mt = 0; mt < 4; mt++) {
            int mRow = b0 + m0w + mt * 16 + (lane >> 2);
            float* p0 = pb + (size_t)mRow * CH + (size_t)t * O;
            float* p1 = p0 + 8 * CH;
#pragma unroll
            for (int nt = 0; nt < 4; nt++) {
                int n = n0 + n0w + nt * 8 + (lane & 3) * 2;
                if (n < O)     { p0[n] = acc[mt][nt][0];     p1[n] = acc[mt][nt][2]; }
                if (n + 1 < O) { p0[n + 1] = acc[mt][nt][1]; p1[n + 1] = acc[mt][nt][3]; }
            }
        }
        return;
    }

    // ---- non-split epilogue: h (+bias) + fused stats partials ----
    float* sS = (float*)smem;
    float* sQ = sS + 128;

    const float* bt = bias + (size_t)t * O;
    float colS[4][2], colQ[4][2];
#pragma unroll
    for (int nt = 0; nt < 4; nt++) { colS[nt][0] = colS[nt][1] = 0.f; colQ[nt][0] = colQ[nt][1] = 0.f; }

#pragma unroll
    for (int mt = 0; mt < 4; mt++) {
        int mRow = b0 + m0w + mt * 16 + (lane >> 2);
        float* h0 = h + (size_t)mRow * CH + (size_t)t * O;
        float* h1 = h0 + 8 * CH;
#pragma unroll
        for (int nt = 0; nt < 4; nt++) {
            int n = n0 + n0w + nt * 8 + (lane & 3) * 2;
            float bv0 = (n < O)     ? __ldg(bt + n)     : 0.f;
            float bv1 = (n + 1 < O) ? __ldg(bt + n + 1) : 0.f;
            float v00 = acc[mt][nt][0] + bv0;
            float v01 = acc[mt][nt][1] + bv1;
            float v10 = acc[mt][nt][2] + bv0;
            float v11 = acc[mt][nt][3] + bv1;
            if (n < O)     { h0[n] = v00;     h1[n] = v10; }
            if (n + 1 < O) { h0[n + 1] = v01; h1[n + 1] = v11; }
            colS[nt][0] += v00 + v10;
            colQ[nt][0] += v00 * v00 + v10 * v10;
            colS[nt][1] += v01 + v11;
            colQ[nt][1] += v01 * v01 + v11 * v11;
        }
    }
#pragma unroll
    for (int nt = 0; nt < 4; nt++)
#pragma unroll
        for (int cc = 0; cc < 2; cc++) {
#pragma unroll
            for (int off = 4; off <= 16; off <<= 1) {
                colS[nt][cc] += __shfl_xor_sync(0xffffffffu, colS[nt][cc], off);
                colQ[nt][cc] += __shfl_xor_sync(0xffffffffu, colQ[nt][cc], off);
            }
        }
    if (wid < 4 && lane < 4) {
#pragma unroll
        for (int nt = 0; nt < 4; nt++)
#pragma unroll
            for (int cc = 0; cc < 2; cc++) {
                int nc = n0w + nt * 8 + lane * 2 + cc;
                sS[nc] = colS[nt][cc];
                sQ[nc] = colQ[nt][cc];
            }
    }
    __syncthreads();
    if (wid >= 4 && lane < 4) {
#pragma unroll
        for (int nt = 0; nt < 4; nt++)
#pragma unroll
            for (int cc = 0; cc < 2; cc++) {
                int nc = n0w + nt * 8 + lane * 2 + cc;
                sS[nc] += colS[nt][cc];
                sQ[nc] += colQ[nt][cc];
            }
    }
    __syncthreads();
    if (tid < 128) {
        int n = n0 + tid;
        if (n < O) {
            g_psum[blockIdx.y * MAXCH + t * O + n] = sS[tid];
            g_psqr[blockIdx.y * MAXCH + t * O + n] = sQ[tid];
        }
    }
}

// ---------------------------------------------------------------------------
// combine: h = sum of kSplit partials + bias; fused 64-row stats partials.
// ---------------------------------------------------------------------------
__global__ void __launch_bounds__(256) combine_kernel(
    const float* __restrict__ bias, int hSel, int CH, int kSplit)
{
    int ch = blockIdx.x * 256 + threadIdx.x;
    if (ch >= CH) return;
    int b0 = blockIdx.y * 64;
    float bv = __ldg(bias + ch);
    float* h = bufptr(hSel);
    float S = 0.f, Q = 0.f;
    for (int b = b0; b < b0 + 64; b++) {
        float v = bv;
        for (int k = 0; k < kSplit; k++)
            v += g_part[((size_t)k * BATCH + b) * CH + ch];
        h[(size_t)b * CH + ch] = v;
        S += v;
        Q += v * v;
    }
    g_psum[blockIdx.y * MAXCH + ch] = S;
    g_psqr[blockIdx.y * MAXCH + ch] = Q;
}

// ---------------------------------------------------------------------------
// stats2: combine nPart deterministic partials -> mu, rstd
// ---------------------------------------------------------------------------
__global__ void __launch_bounds__(256) stats2_kernel(int CH, int nPart)
{
    int ch = blockIdx.x * 256 + threadIdx.x;
    if (ch >= CH) return;
    float S = 0.f, Q = 0.f;
    for (int p = 0; p < nPart; p++) { S += g_psum[p * MAXCH + ch]; Q += g_psqr[p * MAXCH + ch]; }
    float mu  = S * (1.0f / BATCH);
    float var = Q * (1.0f / BATCH) - mu * mu;
    g_mu[ch]   = mu;
    g_rstd[ch] = rsqrtf(var + 1e-5f);
}

// ---------------------------------------------------------------------------
// bn_act_head: fused normalize + tanh (in place) + per-term head dot.
// ---------------------------------------------------------------------------
__global__ void __launch_bounds__(256) bn_act_head_kernel(
    int hSel, const float* __restrict__ gam, const float* __restrict__ bet,
    const float* __restrict__ hw, const float* __restrict__ hb,
    float* __restrict__ out, int O, int CH, int colOff, int nChunk, int chunkSize)
{
    __shared__ float prod[1280];
    int b = blockIdx.x / nChunk;
    int chunk = blockIdx.x - b * nChunk;
    int c0 = chunk * chunkSize;
    float* hrow = bufptr(hSel) + (size_t)b * CH;

    for (int idx = threadIdx.x; idx < chunkSize; idx += 256) {
        int ch = c0 + idx;
        float v = hrow[ch];
        float a = tanh_fast((v - g_mu[ch]) * g_rstd[ch] * __ldg(gam + ch) + __ldg(bet + ch));
        hrow[ch] = a;
        prod[idx] = a * __ldg(hw + ch);
    }
    __syncthreads();

    int termsPerChunk = chunkSize / O;
    if (O == 20) {
        if (threadIdx.x < 64) {
            float s = 0.f;
            const float* p = prod + threadIdx.x * 20;
#pragma unroll
            for (int k = 0; k < 20; k++) s += p[k];
            int t = chunk * 64 + threadIdx.x;
            out[(size_t)b * OUTCOLS + colOff + t] = s + hb[t];
        }
    } else {
        int wid = threadIdx.x >> 5, lane = threadIdx.x & 31;
        for (int tl = wid; tl < termsPerChunk; tl += 8) {
            float s = 0.f;
            for (int k = lane; k < O; k += 32) s += prod[tl * O + k];
#pragma unroll
            for (int off = 16; off; off >>= 1) s += __shfl_xor_sync(0xffffffffu, s, off);
            if (lane == 0) {
                int t = chunk * termsPerChunk + tl;
                out[(size_t)b * OUTCOLS + colOff + t] = s + hb[t];
            }
        }
    }
}

// ---------------------------------------------------------------------------
// Host: s4 -> tiny; s3, s2, s1, s0 -> prep + HMMA GEMM (K-split s1/s0).
// ---------------------------------------------------------------------------
extern "C" void kernel_launch(void* const* d_in, const int* in_sizes, int n_in,
                              void* d_out, int out_size)
{
    const float* x = (const float*)d_in[0];
    float* out = (float*)d_out;

    cudaFuncSetAttribute(mma_gemm_kernel,
                         cudaFuncAttributeMaxDynamicSharedMemorySize, SM_GEMM);

    struct St { int T, I, Ipad, O, Gs, split, CH, colOff, nChunk, kSplit; };
    const St S[5] = {
        {256,   16,   64,   20,   16,    0, 5120,   0, 4, 1},
        { 64,  144,  192,   20,   64,   80, 1280, 256, 1, 1},
        { 16,  336,  384,   77,  256,   80, 1232, 320, 1, 1},
        {  4, 1332, 1344,  308, 1024,  308, 1232, 336, 1, 2},
        {  1, 5328, 5376, 1229, 4096, 1232, 1229, 340, 1, 4},
    };

    int hSel = 0, aSel = -1;
    for (int j = 0; j < 5; j++) {
        const St& s = S[j];
        const float* W  = (const float*)d_in[1 + j * 6 + 0];
        const float* bi = (const float*)d_in[1 + j * 6 + 1];
        const float* ga = (const float*)d_in[1 + j * 6 + 2];
        const float* be = (const float*)d_in[1 + j * 6 + 3];
        const float* hw = (const float*)d_in[1 + j * 6 + 4];
        const float* hb = (const float*)d_in[1 + j * 6 + 5];
        int chPrev = (j > 0) ? S[j - 1].CH : 0;
        int nPart;

        if (j < 1) {
            dim3 grid(BATCH / 512, s.T);
            tiny_kernel<<<grid, 256>>>(aSel, chPrev, x, W, bi, hSel,
                                       s.I, s.Gs, s.split, s.CH);
            nPart = BATCH / 512;
        } else {
            int total4 = BATCH * s.T * (s.Ipad >> 2);
            prepA_kernel<<<(total4 + 255) / 256, 256>>>(aSel, chPrev, x, s.T, s.I,
                                                        s.Ipad, s.Gs, s.split);
            dim3 wg(s.Ipad / 32, (s.O + 31) / 32, s.T);
            prepW_kernel<<<wg, dim3(32, 8)>>>(W, s.I, s.Ipad, s.O);
            dim3 gg((s.O + 127) / 128, BATCH / 128, s.T * s.kSplit);
            mma_gemm_kernel<<<gg, 256, SM_GEMM>>>(bi, hSel, s.T, s.Ipad, s.O, s.CH,
                                                  s.kSplit);
            if (s.kSplit > 1) {
                dim3 cg((s.CH + 255) / 256, 32);
                combine_kernel<<<cg, 256>>>(bi, hSel, s.CH, s.kSplit);
                nPart = 32;
            } else {
                nPart = BATCH / 128;
            }
        }

        stats2_kernel<<<(s.CH + 255) / 256, 256>>>(s.CH, nPart);

        int chunkSize = s.CH / s.nChunk;
        bn_act_head_kernel<<<BATCH * s.nChunk, 256>>>(hSel, ga, be, hw, hb, out,
                                                      s.O, s.CH, s.colOff,
                                                      s.nChunk, chunkSize);
        aSel = hSel;
        hSel ^= 1;
    }
}

// round 12
// speedup vs baseline: 1.0765x; 1.0765x over previous
#include <cuda_runtime.h>
#include <cuda_bf16.h>
#include <math.h>
#include <stdint.h>

#define BATCH   2048
#define NGENES  4096
#define MAXCH   5120
#define OUTCOLS 341

// ---------------------------------------------------------------------------
// Static device buffers
// ---------------------------------------------------------------------------
__device__ float g_bufA[BATCH * MAXCH];
__device__ float g_bufB[BATCH * MAXCH];
__device__ float g_mu[MAXCH];
__device__ float g_rstd[MAXCH];
__device__ float g_psum[32 * MAXCH];
__device__ float g_psqr[32 * MAXCH];
__device__ float g_part[4 * BATCH * 1232];        // K-split partials (40 MB)
__device__ __nv_bfloat16 g_Ahi[12582912];
__device__ __nv_bfloat16 g_Alo[12582912];
__device__ __nv_bfloat16 g_Whi[6607104];
__device__ __nv_bfloat16 g_Wlo[6607104];

__device__ __forceinline__ float* bufptr(int sel) { return sel == 0 ? g_bufA : g_bufB; }

__device__ __forceinline__ uint32_t smem_u32(const void* p) {
    uint32_t a;
    asm("{ .reg .u64 t; cvta.to.shared.u64 t, %1; cvt.u32.u64 %0, t; }" : "=r"(a) : "l"(p));
    return a;
}
__device__ __forceinline__ float tanh_fast(float x) {
    float y;
    asm("tanh.approx.f32 %0, %1;" : "=f"(y) : "f"(x));
    return y;
}
__device__ __forceinline__ uint16_t bf16bits(float v) {
    __nv_bfloat16 h = __float2bfloat16(v);
    return *reinterpret_cast<uint16_t*>(&h);
}
__device__ __forceinline__ float bf16val(uint16_t u) {
    __nv_bfloat16 h = *reinterpret_cast<__nv_bfloat16*>(&u);
    return __bfloat162float(h);
}

#define CP_ASYNC16(dst, src, sz) \
    asm volatile("cp.async.cg.shared.global [%0], [%1], 16, %2;" \
                 :: "r"(dst), "l"(src), "r"(sz))
#define CP_COMMIT()  asm volatile("cp.async.commit_group;" ::: "memory")
#define CP_WAIT(N)   asm volatile("cp.async.wait_group %0;" :: "n"(N) : "memory")

__device__ __forceinline__ void ldsm4(uint32_t& r0, uint32_t& r1, uint32_t& r2,
                                      uint32_t& r3, uint32_t addr) {
    asm volatile("ldmatrix.sync.aligned.m8n8.x4.shared.b16 {%0,%1,%2,%3}, [%4];"
                 : "=r"(r0), "=r"(r1), "=r"(r2), "=r"(r3) : "r"(addr));
}
__device__ __forceinline__ void mma16816(float* d, uint32_t a0, uint32_t a1,
                                         uint32_t a2, uint32_t a3,
                                         uint32_t b0, uint32_t b1) {
    asm volatile("mma.sync.aligned.m16n8k16.row.col.f32.bf16.bf16.f32 "
                 "{%0,%1,%2,%3}, {%4,%5,%6,%7}, {%8,%9}, {%0,%1,%2,%3};"
                 : "+f"(d[0]), "+f"(d[1]), "+f"(d[2]), "+f"(d[3])
                 : "r"(a0), "r"(a1), "r"(a2), "r"(a3), "r"(b0), "r"(b1));
}

// ---------------------------------------------------------------------------
// Tiny-strata GEMM (s4: I=16, s3: I=144; O=20) + fused partial batch stats.
// 256 threads, 512 batch rows/block (2 rows/thread), grid (4, T).
// ---------------------------------------------------------------------------
__global__ void __launch_bounds__(256) tiny_kernel(
    int aSel, int chPrev, const float* __restrict__ x,
    const float* __restrict__ W, const float* __restrict__ bias, int hSel,
    int I, int Gs, int split, int CH)
{
    __shared__ float sW[144 * 20];
    __shared__ float sb2[20];
    __shared__ float sS[8 * 20], sQ[8 * 20];
    const float* act = (aSel >= 0) ? bufptr(aSel) : nullptr;
    float* h = bufptr(hSel);
    int t = blockIdx.y;
    int wid = threadIdx.x >> 5, lane = threadIdx.x & 31;
    const float* Wt = W + (size_t)t * I * 20;
    for (int i = threadIdx.x; i < I * 20; i += 256) sW[i] = Wt[i];
    if (threadIdx.x < 20) sb2[threadIdx.x] = bias[t * 20 + threadIdx.x];
    __syncthreads();

    int b0 = blockIdx.x * 512 + threadIdx.x;
    int b1 = b0 + 256;
    float a0c[20], a1c[20];
#pragma unroll
    for (int o = 0; o < 20; o++) { a0c[o] = sb2[o]; a1c[o] = sb2[o]; }

    const float* w = sW;
    if (split > 0) {
        const float* p0 = act + (size_t)b0 * chPrev + (size_t)t * split;
        const float* p1 = act + (size_t)b1 * chPrev + (size_t)t * split;
        for (int k4 = 0; k4 < split; k4 += 4) {
            float4 v0 = *reinterpret_cast<const float4*>(p0 + k4);
            float4 v1 = *reinterpret_cast<const float4*>(p1 + k4);
            const float a0v[4] = {v0.x, v0.y, v0.z, v0.w};
            const float a1v[4] = {v1.x, v1.y, v1.z, v1.w};
#pragma unroll
            for (int kk = 0; kk < 4; kk++) {
#pragma unroll
                for (int o = 0; o < 20; o++) {
                    float ww = w[o];
                    a0c[o] = fmaf(a0v[kk], ww, a0c[o]);
                    a1c[o] = fmaf(a1v[kk], ww, a1c[o]);
                }
                w += 20;
            }
        }
    }
    {
        const float* q0 = x + (size_t)b0 * NGENES + (size_t)t * Gs;
        const float* q1 = x + (size_t)b1 * NGENES + (size_t)t * Gs;
        int I2 = I - split;
        for (int k4 = 0; k4 < I2; k4 += 4) {
            float4 v0 = *reinterpret_cast<const float4*>(q0 + k4);
            float4 v1 = *reinterpret_cast<const float4*>(q1 + k4);
            const float a0v[4] = {v0.x, v0.y, v0.z, v0.w};
            const float a1v[4] = {v1.x, v1.y, v1.z, v1.w};
#pragma unroll
            for (int kk = 0; kk < 4; kk++) {
#pragma unroll
                for (int o = 0; o < 20; o++) {
                    float ww = w[o];
                    a0c[o] = fmaf(a0v[kk], ww, a0c[o]);
                    a1c[o] = fmaf(a1v[kk], ww, a1c[o]);
                }
                w += 20;
            }
        }
    }
    float* h0 = h + (size_t)b0 * CH + t * 20;
    float* h1 = h + (size_t)b1 * CH + t * 20;
#pragma unroll
    for (int o = 0; o < 20; o++) { h0[o] = a0c[o]; h1[o] = a1c[o]; }

#pragma unroll
    for (int o = 0; o < 20; o++) {
        float s = a0c[o] + a1c[o];
        float q = a0c[o] * a0c[o] + a1c[o] * a1c[o];
#pragma unroll
        for (int off = 16; off; off >>= 1) {
            s += __shfl_xor_sync(0xffffffffu, s, off);
            q += __shfl_xor_sync(0xffffffffu, q, off);
        }
        if (lane == 0) { sS[wid * 20 + o] = s; sQ[wid * 20 + o] = q; }
    }
    __syncthreads();
    if (threadIdx.x < 20) {
        float S = 0.f, Q = 0.f;
#pragma unroll
        for (int ww = 0; ww < 8; ww++) { S += sS[ww * 20 + threadIdx.x]; Q += sQ[ww * 20 + threadIdx.x]; }
        g_psum[blockIdx.x * MAXCH + t * 20 + threadIdx.x] = S;
        g_psqr[blockIdx.x * MAXCH + t * 20 + threadIdx.x] = Q;
    }
}

// ---------------------------------------------------------------------------
// prepA (x4 vectorized): gather + zero-pad + bf16 hi/lo split.
// ---------------------------------------------------------------------------
__global__ void __launch_bounds__(256) prepA_kernel(
    int aSel, int chPrev, const float* __restrict__ x,
    int T, int I, int Ipad, int Gs, int split)
{
    int idx4 = blockIdx.x * 256 + threadIdx.x;
    int TIp4 = T * (Ipad >> 2);
    int b = idx4 / TIp4;
    int rem = idx4 - b * TIp4;
    int t = rem / (Ipad >> 2);
    int i = (rem - t * (Ipad >> 2)) << 2;
    const float* act = (aSel >= 0) ? bufptr(aSel) : nullptr;
    float4 v = make_float4(0.f, 0.f, 0.f, 0.f);
    if (i < split)
        v = *reinterpret_cast<const float4*>(act + (size_t)b * chPrev + t * split + i);
    else if (i < I)
        v = *reinterpret_cast<const float4*>(x + (size_t)b * NGENES + t * Gs + (i - split));
    uint16_t h0 = bf16bits(v.x), h1 = bf16bits(v.y), h2 = bf16bits(v.z), h3 = bf16bits(v.w);
    uint16_t l0 = bf16bits(v.x - bf16val(h0)), l1 = bf16bits(v.y - bf16val(h1));
    uint16_t l2 = bf16bits(v.z - bf16val(h2)), l3 = bf16bits(v.w - bf16val(h3));
    uint2 ph = make_uint2((uint32_t)h0 | ((uint32_t)h1 << 16), (uint32_t)h2 | ((uint32_t)h3 << 16));
    uint2 pl = make_uint2((uint32_t)l0 | ((uint32_t)l1 << 16), (uint32_t)l2 | ((uint32_t)l3 << 16));
    reinterpret_cast<uint2*>(g_Ahi)[idx4] = ph;
    reinterpret_cast<uint2*>(g_Alo)[idx4] = pl;
}

// ---------------------------------------------------------------------------
// prepW: transpose W[t][i][o] -> Wt[t][o][i], pad i to Ipad, bf16 hi/lo.
// ---------------------------------------------------------------------------
__global__ void __launch_bounds__(256) prepW_kernel(
    const float* __restrict__ W, int I, int Ipad, int O)
{
    __shared__ float tile[32][33];
    int t = blockIdx.z;
    int i0 = blockIdx.x * 32, o0 = blockIdx.y * 32;
    int tx = threadIdx.x, ty = threadIdx.y;   // 32 x 8
    const float* Wt = W + (size_t)t * I * O;
#pragma unroll
    for (int j = 0; j < 4; j++) {
        int i = i0 + ty + j * 8, o = o0 + tx;
        tile[ty + j * 8][tx] = (i < I && o < O) ? Wt[(size_t)i * O + o] : 0.f;
    }
    __syncthreads();
#pragma unroll
    for (int j = 0; j < 4; j++) {
        int o = o0 + ty + j * 8, i = i0 + tx;
        if (o < O) {
            float v = tile[tx][ty + j * 8];
            __nv_bfloat16 hi = __float2bfloat16(v);
            size_t oi = ((size_t)t * O + o) * Ipad + i;
            g_Whi[oi] = hi;
            g_Wlo[oi] = __float2bfloat16(v - __bfloat162float(hi));
        }
    }
}

// ---------------------------------------------------------------------------
// HMMA GEMM, optionally K-split. CTA 128x128, 8 warps, K-chunk 32, 3-stage.
// blockIdx.z = t * kSplit + splitIdx.
// ---------------------------------------------------------------------------
#define ROWB     80
#define REG_SZ   10240
#define BUF_SZ   (4 * REG_SZ)
#define SM_GEMM  (3 * BUF_SZ)

__global__ void __launch_bounds__(256, 1) mma_gemm_kernel(
    const float* __restrict__ bias, int hSel, int T, int Ipad, int O, int CH,
    int kSplit)
{
    extern __shared__ char smem[];
    uint32_t sb = smem_u32(smem);
    float* h = bufptr(hSel);
    int tid = threadIdx.x, wid = tid >> 5, lane = tid & 31;
    int t  = blockIdx.z / kSplit;
    int sp = blockIdx.z - t * kSplit;
    int b0 = blockIdx.y * 128, n0 = blockIdx.x * 128;
    int m0w = (wid >> 2) * 64;
    int n0w = (wid & 3) * 32;
    int nCtot = Ipad >> 5;
    int nC = nCtot / kSplit;
    int cBase = sp * nC;
    int Arow = T * Ipad;

    float acc[4][4][4];
#pragma unroll
    for (int a = 0; a < 4; a++)
#pragma unroll
        for (int b = 0; b < 4; b++)
#pragma unroll
            for (int c = 0; c < 4; c++) acc[a][b][c] = 0.f;

    int r0 = (tid + 0) >> 2,   c0 = (tid + 0) & 3;
    int r1 = (tid + 256) >> 2, c1 = (tid + 256) & 3;
    int bn0ok = (n0 + r0 < O) ? 16 : 0;
    int bn1ok = (n0 + r1 < O) ? 16 : 0;
    size_t aOff0 = (size_t)(b0 + r0) * Arow + (size_t)t * Ipad + c0 * 8;
    size_t aOff1 = (size_t)(b0 + r1) * Arow + (size_t)t * Ipad + c1 * 8;
    size_t bOff0 = ((size_t)t * O + min(n0 + r0, O - 1)) * Ipad + c0 * 8;
    size_t bOff1 = ((size_t)t * O + min(n0 + r1, O - 1)) * Ipad + c1 * 8;
    uint32_t d0 = r0 * ROWB + c0 * 16;
    uint32_t d1 = r1 * ROWB + c1 * 16;

#define LOAD_CHUNK(lIdx) do {                                                  \
        uint32_t base = sb + ((lIdx) % 3) * BUF_SZ;                            \
        int k0 = (cBase + (lIdx)) << 5;                                        \
        CP_ASYNC16(base + d0,              g_Ahi + aOff0 + k0, 16);            \
        CP_ASYNC16(base + d1,              g_Ahi + aOff1 + k0, 16);            \
        CP_ASYNC16(base + REG_SZ + d0,     g_Alo + aOff0 + k0, 16);            \
        CP_ASYNC16(base + REG_SZ + d1,     g_Alo + aOff1 + k0, 16);            \
        CP_ASYNC16(base + 2 * REG_SZ + d0, g_Whi + bOff0 + k0, bn0ok);         \
        CP_ASYNC16(base + 2 * REG_SZ + d1, g_Whi + bOff1 + k0, bn1ok);         \
        CP_ASYNC16(base + 3 * REG_SZ + d0, g_Wlo + bOff0 + k0, bn0ok);         \
        CP_ASYNC16(base + 3 * REG_SZ + d1, g_Wlo + bOff1 + k0, bn1ok);         \
        CP_COMMIT();                                                           \
    } while (0)

    uint32_t aRowSel = (lane & 15);
    uint32_t aKHalf  = (lane >> 4) * 16;
    uint32_t bRowSel = (lane & 7) + ((lane >> 4) << 3);
    uint32_t bKHalf  = ((lane >> 3) & 1) * 16;

    LOAD_CHUNK(0);
    LOAD_CHUNK(1);

    for (int l = 0; l < nC; l++) {
        if (l + 2 < nC) LOAD_CHUNK(l + 2);
        else            CP_COMMIT();
        CP_WAIT(2);
        __syncthreads();

        uint32_t base = sb + (l % 3) * BUF_SZ;
        uint32_t aHi = base;
        uint32_t aLo = base + REG_SZ;
        uint32_t bHi = base + 2 * REG_SZ;
        uint32_t bLo = base + 3 * REG_SZ;

#pragma unroll
        for (int ks = 0; ks < 2; ks++) {
            uint32_t kOffA = ks * 32 + aKHalf;
            uint32_t kOffB = ks * 32 + bKHalf;
            uint32_t ah[4][4], al[4][4], bh[4][2], bl[4][2];
#pragma unroll
            for (int mt = 0; mt < 4; mt++) {
                uint32_t ra = (m0w + mt * 16 + aRowSel) * ROWB + kOffA;
                ldsm4(ah[mt][0], ah[mt][1], ah[mt][2], ah[mt][3], aHi + ra);
                ldsm4(al[mt][0], al[mt][1], al[mt][2], al[mt][3], aLo + ra);
            }
#pragma unroll
            for (int np = 0; np < 2; np++) {
                uint32_t rb = (n0w + np * 16 + bRowSel) * ROWB + kOffB;
                uint32_t q0, q1, q2, q3;
                ldsm4(q0, q1, q2, q3, bHi + rb);
                bh[np * 2][0] = q0; bh[np * 2][1] = q1;
                bh[np * 2 + 1][0] = q2; bh[np * 2 + 1][1] = q3;
                ldsm4(q0, q1, q2, q3, bLo + rb);
                bl[np * 2][0] = q0; bl[np * 2][1] = q1;
                bl[np * 2 + 1][0] = q2; bl[np * 2 + 1][1] = q3;
            }
#pragma unroll
            for (int mt = 0; mt < 4; mt++)
#pragma unroll
                for (int nt = 0; nt < 4; nt++) {
                    mma16816(acc[mt][nt], ah[mt][0], ah[mt][1], ah[mt][2], ah[mt][3],
                             bh[nt][0], bh[nt][1]);
                    mma16816(acc[mt][nt], ah[mt][0], ah[mt][1], ah[mt][2], ah[mt][3],
                             bl[nt][0], bl[nt][1]);
                    mma16816(acc[mt][nt], al[mt][0], al[mt][1], al[mt][2], al[mt][3],
                             bh[nt][0], bh[nt][1]);
                }
        }
        __syncthreads();
    }
    CP_WAIT(0);
    __syncthreads();

    if (kSplit > 1) {
        float* pb = g_part + (size_t)sp * BATCH * CH;
#pragma unroll
        for (int mt = 0; mt < 4; mt++) {
            int mRow = b0 + m0w + mt * 16 + (lane >> 2);
            float* p0 = pb + (size_t)mRow * CH + (size_t)t * O;
            float* p1 = p0 + 8 * CH;
#pragma unroll
            for (int nt = 0; nt < 4; nt++) {
                int n = n0 + n0w + nt * 8 + (lane & 3) * 2;
                if (n < O)     { p0[n] = acc[mt][nt][0];     p1[n] = acc[mt][nt][2]; }
                if (n + 1 < O) { p0[n + 1] = acc[mt][nt][1]; p1[n + 1] = acc[mt][nt][3]; }
            }
        }
        return;
    }

    // ---- non-split epilogue: h (+bias) + fused stats partials ----
    float* sS = (float*)smem;
    float* sQ = sS + 128;

    const float* bt = bias + (size_t)t * O;
    float colS[4][2], colQ[4][2];
#pragma unroll
    for (int nt = 0; nt < 4; nt++) { colS[nt][0] = colS[nt][1] = 0.f; colQ[nt][0] = colQ[nt][1] = 0.f; }

#pragma unroll
    for (int mt = 0; mt < 4; mt++) {
        int mRow = b0 + m0w + mt * 16 + (lane >> 2);
        float* h0 = h + (size_t)mRow * CH + (size_t)t * O;
        float* h1 = h0 + 8 * CH;
#pragma unroll
        for (int nt = 0; nt < 4; nt++) {
            int n = n0 + n0w + nt * 8 + (lane & 3) * 2;
            float bv0 = (n < O)     ? __ldg(bt + n)     : 0.f;
            float bv1 = (n + 1 < O) ? __ldg(bt + n + 1) : 0.f;
            float v00 = acc[mt][nt][0] + bv0;
            float v01 = acc[mt][nt][1] + bv1;
            float v10 = acc[mt][nt][2] + bv0;
            float v11 = acc[mt][nt][3] + bv1;
            if (n < O)     { h0[n] = v00;     h1[n] = v10; }
            if (n + 1 < O) { h0[n + 1] = v01; h1[n + 1] = v11; }
            colS[nt][0] += v00 + v10;
            colQ[nt][0] += v00 * v00 + v10 * v10;
            colS[nt][1] += v01 + v11;
            colQ[nt][1] += v01 * v01 + v11 * v11;
        }
    }
#pragma unroll
    for (int nt = 0; nt < 4; nt++)
#pragma unroll
        for (int cc = 0; cc < 2; cc++) {
#pragma unroll
            for (int off = 4; off <= 16; off <<= 1) {
                colS[nt][cc] += __shfl_xor_sync(0xffffffffu, colS[nt][cc], off);
                colQ[nt][cc] += __shfl_xor_sync(0xffffffffu, colQ[nt][cc], off);
            }
        }
    if (wid < 4 && lane < 4) {
#pragma unroll
        for (int nt = 0; nt < 4; nt++)
#pragma unroll
            for (int cc = 0; cc < 2; cc++) {
                int nc = n0w + nt * 8 + lane * 2 + cc;
                sS[nc] = colS[nt][cc];
                sQ[nc] = colQ[nt][cc];
            }
    }
    __syncthreads();
    if (wid >= 4 && lane < 4) {
#pragma unroll
        for (int nt = 0; nt < 4; nt++)
#pragma unroll
            for (int cc = 0; cc < 2; cc++) {
                int nc = n0w + nt * 8 + lane * 2 + cc;
                sS[nc] += colS[nt][cc];
                sQ[nc] += colQ[nt][cc];
            }
    }
    __syncthreads();
    if (tid < 128) {
        int n = n0 + tid;
        if (n < O) {
            g_psum[blockIdx.y * MAXCH + t * O + n] = sS[tid];
            g_psqr[blockIdx.y * MAXCH + t * O + n] = sQ[tid];
        }
    }
}

// ---------------------------------------------------------------------------
// combine: h = sum of kSplit partials + bias; fused 64-row stats partials.
// ---------------------------------------------------------------------------
__global__ void __launch_bounds__(256) combine_kernel(
    const float* __restrict__ bias, int hSel, int CH, int kSplit)
{
    int ch = blockIdx.x * 256 + threadIdx.x;
    if (ch >= CH) return;
    int b0 = blockIdx.y * 64;
    float bv = __ldg(bias + ch);
    float* h = bufptr(hSel);
    float S = 0.f, Q = 0.f;
    for (int b = b0; b < b0 + 64; b++) {
        float v = bv;
        for (int k = 0; k < kSplit; k++)
            v += g_part[((size_t)k * BATCH + b) * CH + ch];
        h[(size_t)b * CH + ch] = v;
        S += v;
        Q += v * v;
    }
    g_psum[blockIdx.y * MAXCH + ch] = S;
    g_psqr[blockIdx.y * MAXCH + ch] = Q;
}

// ---------------------------------------------------------------------------
// stats2: combine nPart deterministic partials -> mu, rstd
// ---------------------------------------------------------------------------
__global__ void __launch_bounds__(256) stats2_kernel(int CH, int nPart)
{
    int ch = blockIdx.x * 256 + threadIdx.x;
    if (ch >= CH) return;
    float S = 0.f, Q = 0.f;
    for (int p = 0; p < nPart; p++) { S += g_psum[p * MAXCH + ch]; Q += g_psqr[p * MAXCH + ch]; }
    float mu  = S * (1.0f / BATCH);
    float var = Q * (1.0f / BATCH) - mu * mu;
    g_mu[ch]   = mu;
    g_rstd[ch] = rsqrtf(var + 1e-5f);
}

// ---------------------------------------------------------------------------
// bn_act_head: fused normalize + tanh (in place) + per-term head dot.
// vec4=1 path: float4 loads/stores (CH, chunkSize multiples of 4).
// ---------------------------------------------------------------------------
__global__ void __launch_bounds__(256) bn_act_head_kernel(
    int hSel, const float* __restrict__ gam, const float* __restrict__ bet,
    const float* __restrict__ hw, const float* __restrict__ hb,
    float* __restrict__ out, int O, int CH, int colOff, int nChunk, int chunkSize,
    int vec4)
{
    __shared__ float prod[1280];
    int b = blockIdx.x / nChunk;
    int chunk = blockIdx.x - b * nChunk;
    int c0 = chunk * chunkSize;
    float* hrow = bufptr(hSel) + (size_t)b * CH;

    if (vec4) {
        int n4 = chunkSize >> 2;
        for (int i4 = threadIdx.x; i4 < n4; i4 += 256) {
            int ch = c0 + i4 * 4;
            float4 v  = *reinterpret_cast<float4*>(hrow + ch);
            float4 mu = *reinterpret_cast<const float4*>(g_mu + ch);
            float4 rs = *reinterpret_cast<const float4*>(g_rstd + ch);
            float4 gg = *reinterpret_cast<const float4*>(gam + ch);
            float4 bb = *reinterpret_cast<const float4*>(bet + ch);
            float4 ww = *reinterpret_cast<const float4*>(hw + ch);
            float4 a;
            a.x = tanh_fast((v.x - mu.x) * rs.x * gg.x + bb.x);
            a.y = tanh_fast((v.y - mu.y) * rs.y * gg.y + bb.y);
            a.z = tanh_fast((v.z - mu.z) * rs.z * gg.z + bb.z);
            a.w = tanh_fast((v.w - mu.w) * rs.w * gg.w + bb.w);
            *reinterpret_cast<float4*>(hrow + ch) = a;
            float4 p;
            p.x = a.x * ww.x; p.y = a.y * ww.y; p.z = a.z * ww.z; p.w = a.w * ww.w;
            *reinterpret_cast<float4*>(prod + i4 * 4) = p;
        }
    } else {
        for (int idx = threadIdx.x; idx < chunkSize; idx += 256) {
            int ch = c0 + idx;
            float v = hrow[ch];
            float a = tanh_fast((v - g_mu[ch]) * g_rstd[ch] * __ldg(gam + ch) + __ldg(bet + ch));
            hrow[ch] = a;
            prod[idx] = a * __ldg(hw + ch);
        }
    }
    __syncthreads();

    int termsPerChunk = chunkSize / O;
    if (O == 20) {
        if (threadIdx.x < 64) {
            float s = 0.f;
            const float* p = prod + threadIdx.x * 20;
#pragma unroll
            for (int k = 0; k < 20; k++) s += p[k];
            int t = chunk * 64 + threadIdx.x;
            out[(size_t)b * OUTCOLS + colOff + t] = s + hb[t];
        }
    } else {
        int wid = threadIdx.x >> 5, lane = threadIdx.x & 31;
        for (int tl = wid; tl < termsPerChunk; tl += 8) {
            float s = 0.f;
            for (int k = lane; k < O; k += 32) s += prod[tl * O + k];
#pragma unroll
            for (int off = 16; off; off >>= 1) s += __shfl_xor_sync(0xffffffffu, s, off);
            if (lane == 0) {
                int t = chunk * termsPerChunk + tl;
                out[(size_t)b * OUTCOLS + colOff + t] = s + hb[t];
            }
        }
    }
}

// ---------------------------------------------------------------------------
// Host: s4, s3 -> tiny; s2, s1, s0 -> prep + HMMA GEMM (K-split s1/s0).
// ---------------------------------------------------------------------------
extern "C" void kernel_launch(void* const* d_in, const int* in_sizes, int n_in,
                              void* d_out, int out_size)
{
    const float* x = (const float*)d_in[0];
    float* out = (float*)d_out;

    cudaFuncSetAttribute(mma_gemm_kernel,
                         cudaFuncAttributeMaxDynamicSharedMemorySize, SM_GEMM);

    struct St { int T, I, Ipad, O, Gs, split, CH, colOff, nChunk, kSplit; };
    const St S[5] = {
        {256,   16,   64,   20,   16,    0, 5120,   0, 4, 1},
        { 64,  144,  192,   20,   64,   80, 1280, 256, 1, 1},
        { 16,  336,  384,   77,  256,   80, 1232, 320, 1, 1},
        {  4, 1332, 1344,  308, 1024,  308, 1232, 336, 1, 2},
        {  1, 5328, 5376, 1229, 4096, 1232, 1229, 340, 1, 4},
    };

    int hSel = 0, aSel = -1;
    for (int j = 0; j < 5; j++) {
        const St& s = S[j];
        const float* W  = (const float*)d_in[1 + j * 6 + 0];
        const float* bi = (const float*)d_in[1 + j * 6 + 1];
        const float* ga = (const float*)d_in[1 + j * 6 + 2];
        const float* be = (const float*)d_in[1 + j * 6 + 3];
        const float* hw = (const float*)d_in[1 + j * 6 + 4];
        const float* hb = (const float*)d_in[1 + j * 6 + 5];
        int chPrev = (j > 0) ? S[j - 1].CH : 0;
        int nPart;

        if (j < 2) {
            dim3 grid(BATCH / 512, s.T);
            tiny_kernel<<<grid, 256>>>(aSel, chPrev, x, W, bi, hSel,
                                       s.I, s.Gs, s.split, s.CH);
            nPart = BATCH / 512;
        } else {
            int total4 = BATCH * s.T * (s.Ipad >> 2);
            prepA_kernel<<<(total4 + 255) / 256, 256>>>(aSel, chPrev, x, s.T, s.I,
                                                        s.Ipad, s.Gs, s.split);
            dim3 wg(s.Ipad / 32, (s.O + 31) / 32, s.T);
            prepW_kernel<<<wg, dim3(32, 8)>>>(W, s.I, s.Ipad, s.O);
            dim3 gg((s.O + 127) / 128, BATCH / 128, s.T * s.kSplit);
            mma_gemm_kernel<<<gg, 256, SM_GEMM>>>(bi, hSel, s.T, s.Ipad, s.O, s.CH,
                                                  s.kSplit);
            if (s.kSplit > 1) {
                dim3 cg((s.CH + 255) / 256, 32);
                combine_kernel<<<cg, 256>>>(bi, hSel, s.CH, s.kSplit);
                nPart = 32;
            } else {
                nPart = BATCH / 128;
            }
        }

        stats2_kernel<<<(s.CH + 255) / 256, 256>>>(s.CH, nPart);

        int chunkSize = s.CH / s.nChunk;
        int vec4 = ((s.CH & 3) == 0 && (chunkSize & 3) == 0) ? 1 : 0;
        bn_act_head_kernel<<<BATCH * s.nChunk, 256>>>(hSel, ga, be, hw, hb, out,
                                                      s.O, s.CH, s.colOff,
                                                      s.nChunk, chunkSize, vec4);
        aSel = hSel;
        hSel ^= 1;
    }
}